// round 5
// baseline (speedup 1.0000x reference)
#include <cuda_runtime.h>
#include <math.h>

#define BB 4
#define SS 4096
#define DD 256
#define MTOT (BB*SS)   // 16384

// ---------------------------------------------------------------------------
// Scratch (allocation-free rule: __device__ globals)
// ---------------------------------------------------------------------------
__device__ __align__(16) float g_qp[MTOT*DD];
__device__ __align__(16) float g_kp[MTOT*DD];
__device__ __align__(16) float g_vp[MTOT*DD];
__device__ __align__(16) float g_ctx[MTOT*DD];

// ---------------------------------------------------------------------------
// Generic projection GEMM: C[M,256] = A[M,256] @ W[256,256] + bias
// BM=BN=64, BK=16, 256 threads, 4x4 microtile
// ---------------------------------------------------------------------------
__global__ __launch_bounds__(256) void proj_gemm(const float* __restrict__ A,
                                                 const float* __restrict__ W,
                                                 const float* __restrict__ bias,
                                                 float* __restrict__ C)
{
    __shared__ float As[16][68];   // k-major: As[k][m]
    __shared__ float Ws[16][68];   // k-major: Ws[k][n]

    const int tid = threadIdx.x;
    const int tx = tid & 15;          // col group
    const int ty = tid >> 4;          // row group
    const int row0 = blockIdx.y * 64;
    const int col0 = blockIdx.x * 64;

    float acc[4][4] = {};

    for (int k0 = 0; k0 < 256; k0 += 16) {
        // A tile 64x16 -> As[k][m]
        {
            int r = tid >> 2;                // 0..63
            int c = (tid & 3) * 4;           // 0,4,8,12
            float4 v = *reinterpret_cast<const float4*>(&A[(size_t)(row0 + r) * 256 + k0 + c]);
            As[c + 0][r] = v.x; As[c + 1][r] = v.y; As[c + 2][r] = v.z; As[c + 3][r] = v.w;
        }
        // W tile 16x64 -> Ws[k][n]
        {
            int r = tid >> 4;                // 0..15
            int c = (tid & 15) * 4;          // 0..60
            float4 v = *reinterpret_cast<const float4*>(&W[(size_t)(k0 + r) * 256 + col0 + c]);
            Ws[r][c + 0] = v.x; Ws[r][c + 1] = v.y; Ws[r][c + 2] = v.z; Ws[r][c + 3] = v.w;
        }
        __syncthreads();

        #pragma unroll
        for (int k = 0; k < 16; k++) {
            float ra[4], rb[4];
            #pragma unroll
            for (int i = 0; i < 4; i++) ra[i] = As[k][ty * 4 + i];
            #pragma unroll
            for (int j = 0; j < 4; j++) rb[j] = Ws[k][tx * 4 + j];
            #pragma unroll
            for (int i = 0; i < 4; i++)
                #pragma unroll
                for (int j = 0; j < 4; j++)
                    acc[i][j] = fmaf(ra[i], rb[j], acc[i][j]);
        }
        __syncthreads();
    }

    #pragma unroll
    for (int i = 0; i < 4; i++) {
        int gr = row0 + ty * 4 + i;
        #pragma unroll
        for (int j = 0; j < 4; j++) {
            int gc = col0 + tx * 4 + j;
            C[(size_t)gr * 256 + gc] = acc[i][j] + bias[gc];
        }
    }
}

// ---------------------------------------------------------------------------
// Scores: logits_tile = (Q_tile @ K_tile^T) * scale, written raw into the attn
// region of d_out. Only tiles with ktile <= qtile are computed (causal);
// entries above the diagonal inside the diagonal tile are garbage but are
// never read by the softmax pass.
// ---------------------------------------------------------------------------
__global__ __launch_bounds__(256) void scores_kernel(const float* __restrict__ qp,
                                                     const float* __restrict__ kp,
                                                     float* __restrict__ attn)
{
    const int kt = blockIdx.x;
    const int qt = blockIdx.y;
    const int b  = blockIdx.z;
    if (kt > qt) return;

    __shared__ float Qs[16][68];   // Qs[d][i]
    __shared__ float Ks[16][68];   // Ks[d][j]

    const int tid = threadIdx.x;
    const int tx = tid & 15;
    const int ty = tid >> 4;
    const int row0 = qt * 64;      // query rows
    const int col0 = kt * 64;      // key rows

    const float* qb = qp + (size_t)b * SS * DD;
    const float* kb = kp + (size_t)b * SS * DD;

    float acc[4][4] = {};

    for (int d0 = 0; d0 < 256; d0 += 16) {
        {
            int r = tid >> 2;
            int c = (tid & 3) * 4;
            float4 v = *reinterpret_cast<const float4*>(&qb[(size_t)(row0 + r) * 256 + d0 + c]);
            Qs[c + 0][r] = v.x; Qs[c + 1][r] = v.y; Qs[c + 2][r] = v.z; Qs[c + 3][r] = v.w;
            float4 w = *reinterpret_cast<const float4*>(&kb[(size_t)(col0 + r) * 256 + d0 + c]);
            Ks[c + 0][r] = w.x; Ks[c + 1][r] = w.y; Ks[c + 2][r] = w.z; Ks[c + 3][r] = w.w;
        }
        __syncthreads();

        #pragma unroll
        for (int k = 0; k < 16; k++) {
            float ra[4], rb[4];
            #pragma unroll
            for (int i = 0; i < 4; i++) ra[i] = Qs[k][ty * 4 + i];
            #pragma unroll
            for (int j = 0; j < 4; j++) rb[j] = Ks[k][tx * 4 + j];
            #pragma unroll
            for (int i = 0; i < 4; i++)
                #pragma unroll
                for (int j = 0; j < 4; j++)
                    acc[i][j] = fmaf(ra[i], rb[j], acc[i][j]);
        }
        __syncthreads();
    }

    const float scale = 0.0625f;   // 1/sqrt(256)
    #pragma unroll
    for (int i = 0; i < 4; i++) {
        int gi = row0 + ty * 4 + i;
        float* rowp = attn + ((size_t)b * SS + gi) * SS;
        #pragma unroll
        for (int j = 0; j < 4; j++) {
            int gj = col0 + tx * 4 + j;
            rowp[gj] = acc[i][j] * scale;
        }
    }
}

// ---------------------------------------------------------------------------
// Row softmax over the causal prefix [0..i]; writes exact zeros for j>i
// (matches exp(-1e9) underflow in the reference). One CTA per row, row cached
// in smem so each element is read once and exp'd once.
// ---------------------------------------------------------------------------
__global__ __launch_bounds__(256) void softmax_kernel(float* __restrict__ attn)
{
    __shared__ float rowbuf[SS];
    __shared__ float red[256];

    const int row = blockIdx.x;          // 0..16383
    const int b = row >> 12;             // /4096
    const int i = row & (SS - 1);
    float* p = attn + ((size_t)b * SS + i) * SS;
    const int n = i + 1;
    const int tid = threadIdx.x;

    float m = -3.0e38f;
    for (int j = tid; j < n; j += 256) {
        float x = p[j];
        rowbuf[j] = x;
        m = fmaxf(m, x);
    }
    red[tid] = m; __syncthreads();
    #pragma unroll
    for (int s = 128; s > 0; s >>= 1) {
        if (tid < s) red[tid] = fmaxf(red[tid], red[tid + s]);
        __syncthreads();
    }
    m = red[0];
    __syncthreads();

    float sum = 0.f;
    for (int j = tid; j < n; j += 256) {
        float e = __expf(rowbuf[j] - m);
        rowbuf[j] = e;
        sum += e;
    }
    red[tid] = sum; __syncthreads();
    #pragma unroll
    for (int s = 128; s > 0; s >>= 1) {
        if (tid < s) red[tid] += red[tid + s];
        __syncthreads();
    }
    const float inv = 1.0f / red[0];

    for (int j = tid; j < n; j += 256) p[j] = rowbuf[j] * inv;
    for (int j = n + tid; j < SS; j += 256) p[j] = 0.0f;
}

// ---------------------------------------------------------------------------
// PV: ctx[b] = attn[b] @ vp[b].  K-loop truncated at the causal boundary
// (attn is exactly zero beyond it).
// ---------------------------------------------------------------------------
__global__ __launch_bounds__(256) void pv_gemm(const float* __restrict__ attn,
                                               const float* __restrict__ vp,
                                               float* __restrict__ ctx)
{
    __shared__ float As[16][68];   // As[k][m]  (attn)
    __shared__ float Vs[16][68];   // Vs[k][n]  (v-proj)

    const int nt = blockIdx.x;     // 0..3
    const int qt = blockIdx.y;     // 0..63
    const int b  = blockIdx.z;
    const int tid = threadIdx.x;
    const int tx = tid & 15;
    const int ty = tid >> 4;
    const int row0 = qt * 64;
    const int col0 = nt * 64;
    const int kend = (qt + 1) * 64;    // causal K extent

    const float* ab = attn + (size_t)b * SS * SS;
    const float* vb = vp + (size_t)b * SS * DD;

    float acc[4][4] = {};

    for (int k0 = 0; k0 < kend; k0 += 16) {
        {
            int r = tid >> 2;
            int c = (tid & 3) * 4;
            float4 v = *reinterpret_cast<const float4*>(&ab[(size_t)(row0 + r) * SS + k0 + c]);
            As[c + 0][r] = v.x; As[c + 1][r] = v.y; As[c + 2][r] = v.z; As[c + 3][r] = v.w;
        }
        {
            int r = tid >> 4;
            int c = (tid & 15) * 4;
            float4 v = *reinterpret_cast<const float4*>(&vb[(size_t)(k0 + r) * 256 + col0 + c]);
            Vs[r][c + 0] = v.x; Vs[r][c + 1] = v.y; Vs[r][c + 2] = v.z; Vs[r][c + 3] = v.w;
        }
        __syncthreads();

        #pragma unroll
        for (int k = 0; k < 16; k++) {
            float ra[4], rb[4];
            #pragma unroll
            for (int i = 0; i < 4; i++) ra[i] = As[k][ty * 4 + i];
            #pragma unroll
            for (int j = 0; j < 4; j++) rb[j] = Vs[k][tx * 4 + j];
            #pragma unroll
            for (int i = 0; i < 4; i++)
                #pragma unroll
                for (int j = 0; j < 4; j++)
                    acc[i][j] = fmaf(ra[i], rb[j], acc[i][j]);
        }
        __syncthreads();
    }

    #pragma unroll
    for (int i = 0; i < 4; i++) {
        int gi = row0 + ty * 4 + i;
        #pragma unroll
        for (int j = 0; j < 4; j++) {
            int gj = col0 + tx * 4 + j;
            ctx[((size_t)b * SS + gi) * DD + gj] = acc[i][j];
        }
    }
}

// ---------------------------------------------------------------------------
// Launch
// inputs: 0 q, 1 k, 2 v, 3 mask(unused; exactly causal), 4 Wq, 5 bq, 6 Wk,
//         7 bk, 8 Wv, 9 bv, 10 Wo, 11 bo
// output: [z (B*S*D f32) | attn (B*S*S f32)]
// ---------------------------------------------------------------------------
extern "C" void kernel_launch(void* const* d_in, const int* in_sizes, int n_in,
                              void* d_out, int out_size)
{
    const float* q  = (const float*)d_in[0];
    const float* k  = (const float*)d_in[1];
    const float* v  = (const float*)d_in[2];
    const float* Wq = (const float*)d_in[4];
    const float* bq = (const float*)d_in[5];
    const float* Wk = (const float*)d_in[6];
    const float* bk = (const float*)d_in[7];
    const float* Wv = (const float*)d_in[8];
    const float* bv = (const float*)d_in[9];
    const float* Wo = (const float*)d_in[10];
    const float* bo = (const float*)d_in[11];

    float* z    = (float*)d_out;
    float* attn = z + (size_t)MTOT * DD;

    float *qp, *kp, *vp, *ctx;
    cudaGetSymbolAddress((void**)&qp,  g_qp);
    cudaGetSymbolAddress((void**)&kp,  g_kp);
    cudaGetSymbolAddress((void**)&vp,  g_vp);
    cudaGetSymbolAddress((void**)&ctx, g_ctx);

    dim3 gproj(256 / 64, MTOT / 64);       // (4, 256)
    proj_gemm<<<gproj, 256>>>(q, Wq, bq, qp);
    proj_gemm<<<gproj, 256>>>(k, Wk, bk, kp);
    proj_gemm<<<gproj, 256>>>(v, Wv, bv, vp);

    dim3 gsc(SS / 64, SS / 64, BB);        // (64, 64, 4)
    scores_kernel<<<gsc, 256>>>(qp, kp, attn);

    softmax_kernel<<<MTOT, 256>>>(attn);

    dim3 gpv(DD / 64, SS / 64, BB);        // (4, 64, 4)
    pv_gemm<<<gpv, 256>>>(attn, vp, ctx);

    proj_gemm<<<gproj, 256>>>(ctx, Wo, bo, z);
}

// round 6
// speedup vs baseline: 1.1111x; 1.1111x over previous
#include <cuda_runtime.h>
#include <math.h>

#define BB 4
#define SS 4096
#define DD 256
#define MTOT (BB*SS)   // 16384

// ---------------------------------------------------------------------------
// Scratch (allocation-free rule: __device__ globals)
// ---------------------------------------------------------------------------
__device__ __align__(16) float g_qp[MTOT*DD];
__device__ __align__(16) float g_kp[MTOT*DD];
__device__ __align__(16) float g_vp[MTOT*DD];
__device__ __align__(16) float g_ctx[MTOT*DD];

// ---------------------------------------------------------------------------
// Shared inner compute: 128x128 tile, 256 threads, 8x8 microtile as 2x2 of
// 4x4 float4 fragments. As/Bs are k-major [16][132] (132 keeps float4 align:
// 132*4 = 528 bytes, multiple of 16).
// ---------------------------------------------------------------------------
#define LDPAD 132

__device__ __forceinline__ void mm_inner(const float (*As)[LDPAD],
                                         const float (*Bs)[LDPAD],
                                         int tx, int ty, float acc[8][8])
{
    #pragma unroll
    for (int k = 0; k < 16; ++k) {
        float4 a0 = *reinterpret_cast<const float4*>(&As[k][ty * 4]);
        float4 a1 = *reinterpret_cast<const float4*>(&As[k][64 + ty * 4]);
        float4 b0 = *reinterpret_cast<const float4*>(&Bs[k][tx * 4]);
        float4 b1 = *reinterpret_cast<const float4*>(&Bs[k][64 + tx * 4]);
        float ra[8] = {a0.x, a0.y, a0.z, a0.w, a1.x, a1.y, a1.z, a1.w};
        float rb[8] = {b0.x, b0.y, b0.z, b0.w, b1.x, b1.y, b1.z, b1.w};
        #pragma unroll
        for (int i = 0; i < 8; ++i)
            #pragma unroll
            for (int j = 0; j < 8; ++j)
                acc[i][j] = fmaf(ra[i], rb[j], acc[i][j]);
    }
}

// Load a 128x16 operand tile (row-major source, rows stride `ld`) transposed
// into k-major smem: Ts[k][m].
__device__ __forceinline__ void load_t_tile(const float* __restrict__ src,
                                            int row0, int k0, int ld,
                                            float (*Ts)[LDPAD], int tid)
{
    int r  = tid >> 2;            // 0..63
    int c4 = (tid & 3) << 2;      // 0,4,8,12
    #pragma unroll
    for (int h = 0; h < 128; h += 64) {
        float4 v = *reinterpret_cast<const float4*>(&src[(size_t)(row0 + r + h) * ld + k0 + c4]);
        Ts[c4 + 0][r + h] = v.x;
        Ts[c4 + 1][r + h] = v.y;
        Ts[c4 + 2][r + h] = v.z;
        Ts[c4 + 3][r + h] = v.w;
    }
}

// Load a 16x128 operand tile (row-major source, rows stride `ld`) directly
// into k-major smem: Ts[k][n].
__device__ __forceinline__ void load_n_tile(const float* __restrict__ src,
                                            int k0, int col0, int ld,
                                            float (*Ts)[LDPAD], int tid)
{
    int kr = tid >> 5;            // 0..7
    int cc = (tid & 31) << 2;     // 0..124
    #pragma unroll
    for (int h = 0; h < 16; h += 8) {
        float4 v = *reinterpret_cast<const float4*>(&src[(size_t)(k0 + kr + h) * ld + col0 + cc]);
        *reinterpret_cast<float4*>(&Ts[kr + h][cc]) = v;
    }
}

// ---------------------------------------------------------------------------
// Projection GEMM: C[M,256] = A[M,256] @ W[256,256] + bias
// ---------------------------------------------------------------------------
__global__ __launch_bounds__(256) void proj_gemm(const float* __restrict__ A,
                                                 const float* __restrict__ W,
                                                 const float* __restrict__ bias,
                                                 float* __restrict__ C)
{
    __shared__ float As[16][LDPAD];
    __shared__ float Bs[16][LDPAD];

    const int tid = threadIdx.x;
    const int tx = tid & 15;
    const int ty = tid >> 4;
    const int row0 = blockIdx.y * 128;
    const int col0 = blockIdx.x * 128;

    float acc[8][8] = {};

    for (int k0 = 0; k0 < 256; k0 += 16) {
        load_t_tile(A, row0, k0, 256, As, tid);
        load_n_tile(W, k0, col0, 256, Bs, tid);
        __syncthreads();
        mm_inner(As, Bs, tx, ty, acc);
        __syncthreads();
    }

    float4 bia0 = *reinterpret_cast<const float4*>(&bias[col0 + tx * 4]);
    float4 bia1 = *reinterpret_cast<const float4*>(&bias[col0 + 64 + tx * 4]);
    #pragma unroll
    for (int i = 0; i < 8; ++i) {
        int gr = row0 + ((i < 4) ? ty * 4 + i : 64 + ty * 4 + (i - 4));
        float4 o0 = make_float4(acc[i][0] + bia0.x, acc[i][1] + bia0.y,
                                acc[i][2] + bia0.z, acc[i][3] + bia0.w);
        float4 o1 = make_float4(acc[i][4] + bia1.x, acc[i][5] + bia1.y,
                                acc[i][6] + bia1.z, acc[i][7] + bia1.w);
        *reinterpret_cast<float4*>(&C[(size_t)gr * 256 + col0 + tx * 4]) = o0;
        *reinterpret_cast<float4*>(&C[(size_t)gr * 256 + col0 + 64 + tx * 4]) = o1;
    }
}

// ---------------------------------------------------------------------------
// Scores: logits = (Q_tile @ K_tile^T) * scale -> attn region (raw).
// Causal: only ktile <= qtile computed. 128x128 tiles.
// ---------------------------------------------------------------------------
__global__ __launch_bounds__(256) void scores_kernel(const float* __restrict__ qp,
                                                     const float* __restrict__ kp,
                                                     float* __restrict__ attn)
{
    const int kt = blockIdx.x;
    const int qt = blockIdx.y;
    const int b  = blockIdx.z;
    if (kt > qt) return;

    __shared__ float As[16][LDPAD];
    __shared__ float Bs[16][LDPAD];

    const int tid = threadIdx.x;
    const int tx = tid & 15;
    const int ty = tid >> 4;
    const int row0 = qt * 128;
    const int col0 = kt * 128;

    const float* qb = qp + (size_t)b * SS * DD;
    const float* kb = kp + (size_t)b * SS * DD;

    float acc[8][8] = {};

    for (int d0 = 0; d0 < 256; d0 += 16) {
        load_t_tile(qb, row0, d0, 256, As, tid);   // Q rows -> As[d][i]
        load_t_tile(kb, col0, d0, 256, Bs, tid);   // K rows -> Bs[d][j]
        __syncthreads();
        mm_inner(As, Bs, tx, ty, acc);
        __syncthreads();
    }

    const float scale = 0.0625f;   // 1/sqrt(256)
    #pragma unroll
    for (int i = 0; i < 8; ++i) {
        int gi = row0 + ((i < 4) ? ty * 4 + i : 64 + ty * 4 + (i - 4));
        float* rowp = attn + ((size_t)b * SS + gi) * SS;
        float4 o0 = make_float4(acc[i][0] * scale, acc[i][1] * scale,
                                acc[i][2] * scale, acc[i][3] * scale);
        float4 o1 = make_float4(acc[i][4] * scale, acc[i][5] * scale,
                                acc[i][6] * scale, acc[i][7] * scale);
        *reinterpret_cast<float4*>(&rowp[col0 + tx * 4]) = o0;
        *reinterpret_cast<float4*>(&rowp[col0 + 64 + tx * 4]) = o1;
    }
}

// ---------------------------------------------------------------------------
// Row softmax over causal prefix [0..i]; exact zeros for j>i.
// ---------------------------------------------------------------------------
__global__ __launch_bounds__(256) void softmax_kernel(float* __restrict__ attn)
{
    __shared__ float rowbuf[SS];
    __shared__ float red[256];

    const int row = blockIdx.x;
    const int b = row >> 12;
    const int i = row & (SS - 1);
    float* p = attn + ((size_t)b * SS + i) * SS;
    const int n = i + 1;
    const int tid = threadIdx.x;

    float m = -3.0e38f;
    for (int j = tid; j < n; j += 256) {
        float x = p[j];
        rowbuf[j] = x;
        m = fmaxf(m, x);
    }
    red[tid] = m; __syncthreads();
    #pragma unroll
    for (int s = 128; s > 0; s >>= 1) {
        if (tid < s) red[tid] = fmaxf(red[tid], red[tid + s]);
        __syncthreads();
    }
    m = red[0];
    __syncthreads();

    float sum = 0.f;
    for (int j = tid; j < n; j += 256) {
        float e = __expf(rowbuf[j] - m);
        rowbuf[j] = e;
        sum += e;
    }
    red[tid] = sum; __syncthreads();
    #pragma unroll
    for (int s = 128; s > 0; s >>= 1) {
        if (tid < s) red[tid] += red[tid + s];
        __syncthreads();
    }
    const float inv = 1.0f / red[0];

    for (int j = tid; j < n; j += 256) p[j] = rowbuf[j] * inv;
    for (int j = n + tid; j < SS; j += 256) p[j] = 0.0f;
}

// ---------------------------------------------------------------------------
// PV: ctx[b] = attn[b] @ vp[b], K-loop truncated at causal boundary.
// 128x128 output tiles (DD=256 -> 2 col tiles).
// ---------------------------------------------------------------------------
__global__ __launch_bounds__(256) void pv_gemm(const float* __restrict__ attn,
                                               const float* __restrict__ vp,
                                               float* __restrict__ ctx)
{
    __shared__ float As[16][LDPAD];
    __shared__ float Bs[16][LDPAD];

    const int nt = blockIdx.x;     // 0..1
    const int qt = blockIdx.y;     // 0..31
    const int b  = blockIdx.z;
    const int tid = threadIdx.x;
    const int tx = tid & 15;
    const int ty = tid >> 4;
    const int row0 = qt * 128;
    const int col0 = nt * 128;
    const int kend = (qt + 1) * 128;

    const float* ab = attn + (size_t)b * SS * SS;
    const float* vb = vp + (size_t)b * SS * DD;

    float acc[8][8] = {};

    for (int k0 = 0; k0 < kend; k0 += 16) {
        load_t_tile(ab, row0, k0, SS, As, tid);    // attn rows -> As[k][m]
        load_n_tile(vb, k0, col0, 256, Bs, tid);   // v rows -> Bs[k][n]
        __syncthreads();
        mm_inner(As, Bs, tx, ty, acc);
        __syncthreads();
    }

    #pragma unroll
    for (int i = 0; i < 8; ++i) {
        int gi = row0 + ((i < 4) ? ty * 4 + i : 64 + ty * 4 + (i - 4));
        float4 o0 = make_float4(acc[i][0], acc[i][1], acc[i][2], acc[i][3]);
        float4 o1 = make_float4(acc[i][4], acc[i][5], acc[i][6], acc[i][7]);
        *reinterpret_cast<float4*>(&ctx[((size_t)b * SS + gi) * DD + col0 + tx * 4]) = o0;
        *reinterpret_cast<float4*>(&ctx[((size_t)b * SS + gi) * DD + col0 + 64 + tx * 4]) = o1;
    }
}

// ---------------------------------------------------------------------------
// Launch
// inputs: 0 q, 1 k, 2 v, 3 mask(unused; exactly causal), 4 Wq, 5 bq, 6 Wk,
//         7 bk, 8 Wv, 9 bv, 10 Wo, 11 bo
// output: [z (B*S*D f32) | attn (B*S*S f32)]
// ---------------------------------------------------------------------------
extern "C" void kernel_launch(void* const* d_in, const int* in_sizes, int n_in,
                              void* d_out, int out_size)
{
    const float* q  = (const float*)d_in[0];
    const float* k  = (const float*)d_in[1];
    const float* v  = (const float*)d_in[2];
    const float* Wq = (const float*)d_in[4];
    const float* bq = (const float*)d_in[5];
    const float* Wk = (const float*)d_in[6];
    const float* bk = (const float*)d_in[7];
    const float* Wv = (const float*)d_in[8];
    const float* bv = (const float*)d_in[9];
    const float* Wo = (const float*)d_in[10];
    const float* bo = (const float*)d_in[11];

    float* z    = (float*)d_out;
    float* attn = z + (size_t)MTOT * DD;

    float *qp, *kp, *vp, *ctx;
    cudaGetSymbolAddress((void**)&qp,  g_qp);
    cudaGetSymbolAddress((void**)&kp,  g_kp);
    cudaGetSymbolAddress((void**)&vp,  g_vp);
    cudaGetSymbolAddress((void**)&ctx, g_ctx);

    dim3 gproj(256 / 128, MTOT / 128);     // (2, 128)
    proj_gemm<<<gproj, 256>>>(q, Wq, bq, qp);
    proj_gemm<<<gproj, 256>>>(k, Wk, bk, kp);
    proj_gemm<<<gproj, 256>>>(v, Wv, bv, vp);

    dim3 gsc(SS / 128, SS / 128, BB);      // (32, 32, 4)
    scores_kernel<<<gsc, 256>>>(qp, kp, attn);

    softmax_kernel<<<MTOT, 256>>>(attn);

    dim3 gpv(DD / 128, SS / 128, BB);      // (2, 32, 4)
    pv_gemm<<<gpv, 256>>>(attn, vp, ctx);

    proj_gemm<<<gproj, 256>>>(ctx, Wo, bo, z);
}

// round 13
// speedup vs baseline: 1.7913x; 1.6122x over previous
#include <cuda_runtime.h>
#include <cuda_bf16.h>
#include <stdint.h>
#include <math.h>

#define BB 4
#define SS 4096
#define DD 256
#define MTOT (BB*SS)   // 16384

// ---------------------------------------------------------------------------
// Scratch (__device__ globals; allocation-free rule)
// ---------------------------------------------------------------------------
__device__ __align__(16) __nv_bfloat16 g_qhi[MTOT*DD];
__device__ __align__(16) __nv_bfloat16 g_qlo[MTOT*DD];
__device__ __align__(16) __nv_bfloat16 g_khi[MTOT*DD];
__device__ __align__(16) __nv_bfloat16 g_klo[MTOT*DD];
__device__ __align__(16) __nv_bfloat16 g_vhi[MTOT*DD];   // transposed [b][d][s]
__device__ __align__(16) __nv_bfloat16 g_vlo[MTOT*DD];   // transposed [b][d][s]
__device__ __align__(16) __nv_bfloat16 g_ahi[67108864];  // attn hi [MTOT][SS]
__device__ __align__(16) __nv_bfloat16 g_alo[67108864];  // attn lo
__device__ __align__(16) __nv_bfloat16 g_chi[MTOT*DD];   // ctx hi [MTOT][DD]
__device__ __align__(16) __nv_bfloat16 g_clo[MTOT*DD];

// ---------------------------------------------------------------------------
// smem: four 128x32 bf16 operand tiles, row stride 40 bf16 (80B) for
// conflict-free ldmatrix. 4 x 10240 B = 40960 B static shared.
// ---------------------------------------------------------------------------
#define TSTRIDE 40
#define TBYTES  (128 * TSTRIDE * 2)   // 10240
#define O_AHI 0
#define O_ALO TBYTES
#define O_BHI (2*TBYTES)
#define O_BLO (3*TBYTES)

__device__ __forceinline__ uint32_t smem_u32(const void* p) {
    uint32_t a;
    asm("{ .reg .u64 t; cvta.to.shared.u64 t, %1; cvt.u32.u64 %0, t; }" : "=r"(a) : "l"(p));
    return a;
}

__device__ __forceinline__ void ldm_x4(uint32_t* r, uint32_t addr) {
    asm volatile("ldmatrix.sync.aligned.m8n8.x4.shared.b16 {%0,%1,%2,%3}, [%4];"
                 : "=r"(r[0]), "=r"(r[1]), "=r"(r[2]), "=r"(r[3]) : "r"(addr));
}

__device__ __forceinline__ void mma16816(float* c, const uint32_t* a, const uint32_t* b) {
    asm volatile("mma.sync.aligned.m16n8k16.row.col.f32.bf16.bf16.f32 "
                 "{%0,%1,%2,%3}, {%4,%5,%6,%7}, {%8,%9}, {%0,%1,%2,%3};"
                 : "+f"(c[0]), "+f"(c[1]), "+f"(c[2]), "+f"(c[3])
                 : "r"(a[0]), "r"(a[1]), "r"(a[2]), "r"(a[3]), "r"(b[0]), "r"(b[1]));
}

__device__ __forceinline__ void split2(float x, uint16_t& h, uint16_t& l) {
    __nv_bfloat16 hb = __float2bfloat16(x);
    __nv_bfloat16 lb = __float2bfloat16(x - __bfloat162float(hb));
    h = *(uint16_t*)&hb;
    l = *(uint16_t*)&lb;
}
__device__ __forceinline__ uint32_t pk(uint16_t a, uint16_t b) {
    return (uint32_t)a | ((uint32_t)b << 16);
}

// ---------------------------------------------------------------------------
// Staging (256 threads). All tiles are 128 rows x 32 cols bf16, stride 40.
// ---------------------------------------------------------------------------
// copy bf16 128x32 slice (ld_e elements per source row)
__device__ __forceinline__ void stage_bf16_40(const __nv_bfloat16* src, size_t ld_e,
                                              uint16_t* dst, int tid)
{
    #pragma unroll
    for (int i = 0; i < 4; i++) {
        int u = tid + i * 256;            // 1024 uint2 units (4 bf16)
        int row = u >> 3, c4 = (u & 7) * 4;
        uint2 v = *(const uint2*)(src + (size_t)row * ld_e + c4);
        *(uint2*)(dst + row * TSTRIDE + c4) = v;
    }
}
// convert f32 128x32 slice -> hi/lo
__device__ __forceinline__ void stage_cvtA_40(const float* src, size_t ld,
                                              uint16_t* dhi, uint16_t* dlo, int tid)
{
    #pragma unroll
    for (int i = 0; i < 4; i++) {
        int u = tid + i * 256;            // 1024 float4 units
        int row = u >> 3, c4 = (u & 7) * 4;
        float4 v = *(const float4*)(src + (size_t)row * ld + c4);
        uint16_t hx, lx, hy, ly, hz, lz, hw, lw;
        split2(v.x, hx, lx); split2(v.y, hy, ly);
        split2(v.z, hz, lz); split2(v.w, hw, lw);
        *(uint2*)(dhi + row * TSTRIDE + c4) = make_uint2(pk(hx, hy), pk(hz, hw));
        *(uint2*)(dlo + row * TSTRIDE + c4) = make_uint2(pk(lx, ly), pk(lz, lw));
    }
}
// convert + transpose W block [32 k][128 n] f32 -> [n][k] hi/lo
__device__ __forceinline__ void stage_cvtW_40(const float* W, size_t ldw,
                                              uint16_t* dhi, uint16_t* dlo, int tid)
{
    #pragma unroll
    for (int i = 0; i < 4; i++) {
        int u = tid + i * 256;            // 1024 float4 units over 32x128
        int kr = u >> 5, n4 = (u & 31) * 4;
        float4 v = *(const float4*)(W + (size_t)kr * ldw + n4);
        float a[4] = {v.x, v.y, v.z, v.w};
        #pragma unroll
        for (int j = 0; j < 4; j++) {
            uint16_t h, l; split2(a[j], h, l);
            dhi[(n4 + j) * TSTRIDE + kr] = h;
            dlo[(n4 + j) * TSTRIDE + kr] = l;
        }
    }
}

// ---------------------------------------------------------------------------
// Warp mainloop over one staged BK=32 chunk. Warp tile 64(m) x 32(n).
// acc[mi][ni][4], mi<4 (m16), ni<4 (n8).
// ---------------------------------------------------------------------------
__device__ __forceinline__ void warp_mma_chunk(float acc[4][4][4],
                                               uint32_t sb, int wm, int wn, int lane)
{
    #pragma unroll
    for (int kk = 0; kk < 32; kk += 16) {
        uint32_t Ah[4][4], Al[4][4];
        const int mrow = wm + (lane & 15);
        const int kA = kk + ((lane >> 4) << 3);
        #pragma unroll
        for (int mi = 0; mi < 4; mi++) {
            uint32_t off = (uint32_t)((mrow + mi * 16) * TSTRIDE + kA) * 2;
            ldm_x4(Ah[mi], sb + O_AHI + off);
            ldm_x4(Al[mi], sb + O_ALO + off);
        }
        const int nrow0 = wn + (lane & 7) + ((lane >> 4) << 3);
        const int kB = kk + (((lane >> 3) & 1) << 3);
        #pragma unroll
        for (int np = 0; np < 2; np++) {
            uint32_t Bh[4], Bl[4];
            uint32_t off = (uint32_t)((nrow0 + np * 16) * TSTRIDE + kB) * 2;
            ldm_x4(Bh, sb + O_BHI + off);
            ldm_x4(Bl, sb + O_BLO + off);
            #pragma unroll
            for (int mi = 0; mi < 4; mi++)
                #pragma unroll
                for (int nj = 0; nj < 2; nj++) {
                    float* c = acc[mi][np * 2 + nj];
                    mma16816(c, Ah[mi], Bh + nj * 2);
                    mma16816(c, Ah[mi], Bl + nj * 2);
                    mma16816(c, Al[mi], Bh + nj * 2);
                }
        }
    }
}

// ---------------------------------------------------------------------------
// Q/K projection: out hi/lo [MTOT][DD]
// ---------------------------------------------------------------------------
__global__ __launch_bounds__(256) void proj_qk_mma(const float* __restrict__ A,
                                                   const float* __restrict__ W,
                                                   const float* __restrict__ bias,
                                                   __nv_bfloat16* __restrict__ dhi,
                                                   __nv_bfloat16* __restrict__ dlo)
{
    __shared__ __align__(16) uint8_t smem[4 * TBYTES];
    const int tid = threadIdx.x, lane = tid & 31, wid = tid >> 5;
    const int wm = (wid & 1) * 64, wn = (wid >> 1) * 32;
    const int row0 = blockIdx.y * 128, col0 = blockIdx.x * 128;
    uint32_t sb = smem_u32(smem);
    uint16_t* sm = (uint16_t*)smem;

    float acc[4][4][4] = {};
    for (int k0 = 0; k0 < 256; k0 += 32) {
        stage_cvtA_40(A + (size_t)row0 * DD + k0, DD, sm + O_AHI/2, sm + O_ALO/2, tid);
        stage_cvtW_40(W + (size_t)k0 * DD + col0, DD, sm + O_BHI/2, sm + O_BLO/2, tid);
        __syncthreads();
        warp_mma_chunk(acc, sb, wm, wn, lane);
        __syncthreads();
    }

    const int r = lane >> 2, cq = (lane & 3) * 2;
    #pragma unroll
    for (int mi = 0; mi < 4; mi++) {
        #pragma unroll
        for (int ni = 0; ni < 4; ni++) {
            int gc = col0 + wn + ni * 8 + cq;
            float b0 = bias[gc], b1 = bias[gc + 1];
            #pragma unroll
            for (int h = 0; h < 2; h++) {
                int gr = row0 + wm + mi * 16 + r + h * 8;
                float x0 = acc[mi][ni][h * 2] + b0, x1 = acc[mi][ni][h * 2 + 1] + b1;
                uint16_t h0, l0, h1, l1;
                split2(x0, h0, l0); split2(x1, h1, l1);
                *(uint32_t*)(dhi + (size_t)gr * DD + gc) = pk(h0, h1);
                *(uint32_t*)(dlo + (size_t)gr * DD + gc) = pk(l0, l1);
            }
        }
    }
}

// ---------------------------------------------------------------------------
// V projection: out hi/lo transposed [b][d][s]; transpose via smem reuse
// ---------------------------------------------------------------------------
__global__ __launch_bounds__(256) void proj_v_mma(const float* __restrict__ A,
                                                  const float* __restrict__ W,
                                                  const float* __restrict__ bias,
                                                  __nv_bfloat16* __restrict__ vhi,
                                                  __nv_bfloat16* __restrict__ vlo)
{
    __shared__ __align__(16) uint8_t smem[4 * TBYTES];
    const int tid = threadIdx.x, lane = tid & 31, wid = tid >> 5;
    const int wm = (wid & 1) * 64, wn = (wid >> 1) * 32;
    const int row0 = blockIdx.y * 128, col0 = blockIdx.x * 128;
    uint32_t sb = smem_u32(smem);
    uint16_t* sm = (uint16_t*)smem;

    float acc[4][4][4] = {};
    for (int k0 = 0; k0 < 256; k0 += 32) {
        stage_cvtA_40(A + (size_t)row0 * DD + k0, DD, sm + O_AHI/2, sm + O_ALO/2, tid);
        stage_cvtW_40(W + (size_t)k0 * DD + col0, DD, sm + O_BHI/2, sm + O_BLO/2, tid);
        __syncthreads();
        warp_mma_chunk(acc, sb, wm, wn, lane);
        __syncthreads();
    }

    // two passes (hi, lo) through a 128x128 bf16 transpose buffer [d][tok]
    const int r = lane >> 2, cq = (lane & 3) * 2;
    const int b = row0 >> 12, tok0 = row0 & (SS - 1);
    #pragma unroll
    for (int plane = 0; plane < 2; plane++) {
        uint16_t* tb = (uint16_t*)smem;   // [128 d][128 tok]
        #pragma unroll
        for (int mi = 0; mi < 4; mi++)
            #pragma unroll
            for (int ni = 0; ni < 4; ni++) {
                int d0 = wn + ni * 8 + cq;
                float b0 = bias[col0 + d0], b1 = bias[col0 + d0 + 1];
                #pragma unroll
                for (int h = 0; h < 2; h++) {
                    int m = wm + mi * 16 + r + h * 8;
                    float x0 = acc[mi][ni][h * 2] + b0, x1 = acc[mi][ni][h * 2 + 1] + b1;
                    uint16_t h0, l0, h1, l1;
                    split2(x0, h0, l0); split2(x1, h1, l1);
                    tb[d0 * 128 + m] = plane ? l0 : h0;
                    tb[(d0 + 1) * 128 + m] = plane ? l1 : h1;
                }
            }
        __syncthreads();
        // coalesced copy out: 128 rows (d), 256B each
        for (int d = wid; d < 128; d += 8) {
            uint2 v = *(const uint2*)(tb + d * 128 + lane * 4);
            __nv_bfloat16* dst = (plane ? vlo : vhi) + ((size_t)b * DD + col0 + d) * SS + tok0;
            *(uint2*)((uint16_t*)dst + lane * 4) = v;
        }
        __syncthreads();
    }
}

// ---------------------------------------------------------------------------
// O projection: A = ctx hi/lo bf16, out z fp32 (+bias)
// ---------------------------------------------------------------------------
__global__ __launch_bounds__(256) void proj_o_mma(const __nv_bfloat16* __restrict__ chi,
                                                  const __nv_bfloat16* __restrict__ clo,
                                                  const float* __restrict__ W,
                                                  const float* __restrict__ bias,
                                                  float* __restrict__ z)
{
    __shared__ __align__(16) uint8_t smem[4 * TBYTES];
    const int tid = threadIdx.x, lane = tid & 31, wid = tid >> 5;
    const int wm = (wid & 1) * 64, wn = (wid >> 1) * 32;
    const int row0 = blockIdx.y * 128, col0 = blockIdx.x * 128;
    uint32_t sb = smem_u32(smem);
    uint16_t* sm = (uint16_t*)smem;

    float acc[4][4][4] = {};
    for (int k0 = 0; k0 < 256; k0 += 32) {
        stage_bf16_40(chi + (size_t)row0 * DD + k0, DD, sm + O_AHI/2, tid);
        stage_bf16_40(clo + (size_t)row0 * DD + k0, DD, sm + O_ALO/2, tid);
        stage_cvtW_40(W + (size_t)k0 * DD + col0, DD, sm + O_BHI/2, sm + O_BLO/2, tid);
        __syncthreads();
        warp_mma_chunk(acc, sb, wm, wn, lane);
        __syncthreads();
    }

    const int r = lane >> 2, cq = (lane & 3) * 2;
    #pragma unroll
    for (int mi = 0; mi < 4; mi++)
        #pragma unroll
        for (int ni = 0; ni < 4; ni++) {
            int gc = col0 + wn + ni * 8 + cq;
            float b0 = bias[gc], b1 = bias[gc + 1];
            #pragma unroll
            for (int h = 0; h < 2; h++) {
                int gr = row0 + wm + mi * 16 + r + h * 8;
                float2 o = make_float2(acc[mi][ni][h * 2] + b0, acc[mi][ni][h * 2 + 1] + b1);
                *(float2*)(z + (size_t)gr * DD + gc) = o;
            }
        }
}

// ---------------------------------------------------------------------------
// Scores: logits = Q@K^T * scale -> attn region (causal tiles only)
// ---------------------------------------------------------------------------
__global__ __launch_bounds__(256) void scores_mma(const __nv_bfloat16* __restrict__ qhi,
                                                  const __nv_bfloat16* __restrict__ qlo,
                                                  const __nv_bfloat16* __restrict__ khi,
                                                  const __nv_bfloat16* __restrict__ klo,
                                                  float* __restrict__ attn)
{
    const int kt = blockIdx.x, qt = blockIdx.y, b = blockIdx.z;
    if (kt > qt) return;
    __shared__ __align__(16) uint8_t smem[4 * TBYTES];
    const int tid = threadIdx.x, lane = tid & 31, wid = tid >> 5;
    const int wm = (wid & 1) * 64, wn = (wid >> 1) * 32;
    uint32_t sb = smem_u32(smem);
    uint16_t* sm = (uint16_t*)smem;

    const size_t abase = ((size_t)b * SS + qt * 128) * DD;
    const size_t bbase = ((size_t)b * SS + kt * 128) * DD;

    float acc[4][4][4] = {};
    for (int d0 = 0; d0 < 256; d0 += 32) {
        stage_bf16_40(qhi + abase + d0, DD, sm + O_AHI/2, tid);
        stage_bf16_40(qlo + abase + d0, DD, sm + O_ALO/2, tid);
        stage_bf16_40(khi + bbase + d0, DD, sm + O_BHI/2, tid);
        stage_bf16_40(klo + bbase + d0, DD, sm + O_BLO/2, tid);
        __syncthreads();
        warp_mma_chunk(acc, sb, wm, wn, lane);
        __syncthreads();
    }

    const int r = lane >> 2, cq = (lane & 3) * 2;
    const float scale = 0.0625f;
    #pragma unroll
    for (int mi = 0; mi < 4; mi++)
        #pragma unroll
        for (int ni = 0; ni < 4; ni++) {
            int gc = kt * 128 + wn + ni * 8 + cq;
            #pragma unroll
            for (int h = 0; h < 2; h++) {
                int gr = qt * 128 + wm + mi * 16 + r + h * 8;
                float2 o = make_float2(acc[mi][ni][h * 2] * scale,
                                       acc[mi][ni][h * 2 + 1] * scale);
                *(float2*)(attn + ((size_t)b * SS + gr) * SS + gc) = o;
            }
        }
}

// ---------------------------------------------------------------------------
// Row softmax (causal prefix); emits fp32 attn + bf16 hi/lo operand copies
// ---------------------------------------------------------------------------
__global__ __launch_bounds__(256) void softmax_kernel(float* __restrict__ attn,
                                                      __nv_bfloat16* __restrict__ ahi,
                                                      __nv_bfloat16* __restrict__ alo)
{
    __shared__ float rowbuf[SS];
    __shared__ float red[256];

    const int row = blockIdx.x;
    const int b = row >> 12;
    const int i = row & (SS - 1);
    const size_t rbase = ((size_t)b * SS + i) * SS;
    float* p = attn + rbase;
    const int n = i + 1;
    const int tid = threadIdx.x;

    float m = -3.0e38f;
    for (int j = tid; j < n; j += 256) {
        float x = p[j];
        rowbuf[j] = x;
        m = fmaxf(m, x);
    }
    red[tid] = m; __syncthreads();
    #pragma unroll
    for (int s = 128; s > 0; s >>= 1) {
        if (tid < s) red[tid] = fmaxf(red[tid], red[tid + s]);
        __syncthreads();
    }
    m = red[0];
    __syncthreads();

    float sum = 0.f;
    for (int j = tid; j < n; j += 256) {
        float e = __expf(rowbuf[j] - m);
        rowbuf[j] = e;
        sum += e;
    }
    red[tid] = sum; __syncthreads();
    #pragma unroll
    for (int s = 128; s > 0; s >>= 1) {
        if (tid < s) red[tid] += red[tid + s];
        __syncthreads();
    }
    const float inv = 1.0f / red[0];

    for (int j = tid; j < n; j += 256) {
        float a = rowbuf[j] * inv;
        p[j] = a;
        uint16_t h, l; split2(a, h, l);
        ((uint16_t*)ahi)[rbase + j] = h;
        ((uint16_t*)alo)[rbase + j] = l;
    }
    const int kend = (i & ~127) + 128;   // PV reads up to tile boundary
    for (int j = n + tid; j < kend; j += 256) {
        ((uint16_t*)ahi)[rbase + j] = 0;
        ((uint16_t*)alo)[rbase + j] = 0;
    }
    for (int j = n + tid; j < SS; j += 256) p[j] = 0.0f;
}

// ---------------------------------------------------------------------------
// PV: ctx = attn @ V (K truncated at causal boundary); out ctx hi/lo bf16
// ---------------------------------------------------------------------------
__global__ __launch_bounds__(256) void pv_mma(const __nv_bfloat16* __restrict__ ahi,
                                              const __nv_bfloat16* __restrict__ alo,
                                              const __nv_bfloat16* __restrict__ vhi,
                                              const __nv_bfloat16* __restrict__ vlo,
                                              __nv_bfloat16* __restrict__ chi,
                                              __nv_bfloat16* __restrict__ clo)
{
    const int nt = blockIdx.x, qt = blockIdx.y, b = blockIdx.z;
    __shared__ __align__(16) uint8_t smem[4 * TBYTES];
    const int tid = threadIdx.x, lane = tid & 31, wid = tid >> 5;
    const int wm = (wid & 1) * 64, wn = (wid >> 1) * 32;
    uint32_t sb = smem_u32(smem);
    uint16_t* sm = (uint16_t*)smem;

    const int kend = (qt + 1) * 128;
    const size_t abase = ((size_t)b * SS + qt * 128) * SS;
    const size_t vbase = ((size_t)b * DD + nt * 128) * SS;

    float acc[4][4][4] = {};
    for (int k0 = 0; k0 < kend; k0 += 32) {
        stage_bf16_40(ahi + abase + k0, SS, sm + O_AHI/2, tid);
        stage_bf16_40(alo + abase + k0, SS, sm + O_ALO/2, tid);
        stage_bf16_40(vhi + vbase + k0, SS, sm + O_BHI/2, tid);
        stage_bf16_40(vlo + vbase + k0, SS, sm + O_BLO/2, tid);
        __syncthreads();
        warp_mma_chunk(acc, sb, wm, wn, lane);
        __syncthreads();
    }

    const int r = lane >> 2, cq = (lane & 3) * 2;
    #pragma unroll
    for (int mi = 0; mi < 4; mi++)
        #pragma unroll
        for (int ni = 0; ni < 4; ni++) {
            int gc = nt * 128 + wn + ni * 8 + cq;
            #pragma unroll
            for (int h = 0; h < 2; h++) {
                size_t gr = (size_t)b * SS + qt * 128 + wm + mi * 16 + r + h * 8;
                uint16_t h0, l0, h1, l1;
                split2(acc[mi][ni][h * 2], h0, l0);
                split2(acc[mi][ni][h * 2 + 1], h1, l1);
                *(uint32_t*)(chi + gr * DD + gc) = pk(h0, h1);
                *(uint32_t*)(clo + gr * DD + gc) = pk(l0, l1);
            }
        }
}

// ---------------------------------------------------------------------------
// Launch
// inputs: 0 q, 1 k, 2 v, 3 mask(unused; exactly causal), 4 Wq, 5 bq, 6 Wk,
//         7 bk, 8 Wv, 9 bv, 10 Wo, 11 bo
// output: [z (B*S*D f32) | attn (B*S*S f32)]
// ---------------------------------------------------------------------------
extern "C" void kernel_launch(void* const* d_in, const int* in_sizes, int n_in,
                              void* d_out, int out_size)
{
    const float* q  = (const float*)d_in[0];
    const float* k  = (const float*)d_in[1];
    const float* v  = (const float*)d_in[2];
    const float* Wq = (const float*)d_in[4];
    const float* bq = (const float*)d_in[5];
    const float* Wk = (const float*)d_in[6];
    const float* bk = (const float*)d_in[7];
    const float* Wv = (const float*)d_in[8];
    const float* bv = (const float*)d_in[9];
    const float* Wo = (const float*)d_in[10];
    const float* bo = (const float*)d_in[11];

    float* z    = (float*)d_out;
    float* attn = z + (size_t)MTOT * DD;

    __nv_bfloat16 *qhi, *qlo, *khi, *klo, *vhi, *vlo, *ahi, *alo, *chi, *clo;
    cudaGetSymbolAddress((void**)&qhi, g_qhi);
    cudaGetSymbolAddress((void**)&qlo, g_qlo);
    cudaGetSymbolAddress((void**)&khi, g_khi);
    cudaGetSymbolAddress((void**)&klo, g_klo);
    cudaGetSymbolAddress((void**)&vhi, g_vhi);
    cudaGetSymbolAddress((void**)&vlo, g_vlo);
    cudaGetSymbolAddress((void**)&ahi, g_ahi);
    cudaGetSymbolAddress((void**)&alo, g_alo);
    cudaGetSymbolAddress((void**)&chi, g_chi);
    cudaGetSymbolAddress((void**)&clo, g_clo);

    dim3 gproj(2, 128);
    proj_qk_mma<<<gproj, 256>>>(q, Wq, bq, qhi, qlo);
    proj_qk_mma<<<gproj, 256>>>(k, Wk, bk, khi, klo);
    proj_v_mma <<<gproj, 256>>>(v, Wv, bv, vhi, vlo);

    dim3 gsc(32, 32, 4);
    scores_mma<<<gsc, 256>>>(qhi, qlo, khi, klo, attn);

    softmax_kernel<<<MTOT, 256>>>(attn, ahi, alo);

    dim3 gpv(2, 32, 4);
    pv_mma<<<gpv, 256>>>(ahi, alo, vhi, vlo, chi, clo);

    proj_o_mma<<<gproj, 256>>>(chi, clo, Wo, bo, z);
}

// round 15
// speedup vs baseline: 1.9751x; 1.1026x over previous
#include <cuda_runtime.h>
#include <cuda_bf16.h>
#include <stdint.h>
#include <math.h>

#define BB 4
#define SS 4096
#define DD 256
#define MTOT (BB*SS)   // 16384

// ---------------------------------------------------------------------------
// Scratch (__device__ globals; allocation-free rule)
// ---------------------------------------------------------------------------
__device__ __align__(16) __nv_bfloat16 g_qhi[MTOT*DD];
__device__ __align__(16) __nv_bfloat16 g_qlo[MTOT*DD];
__device__ __align__(16) __nv_bfloat16 g_khi[MTOT*DD];
__device__ __align__(16) __nv_bfloat16 g_klo[MTOT*DD];
__device__ __align__(16) __nv_bfloat16 g_vhi[MTOT*DD];   // transposed [b][d][s]
__device__ __align__(16) __nv_bfloat16 g_vlo[MTOT*DD];   // transposed [b][d][s]
__device__ __align__(16) __nv_bfloat16 g_ahi[67108864];  // attn hi [MTOT][SS]
__device__ __align__(16) __nv_bfloat16 g_alo[67108864];  // attn lo
__device__ __align__(16) __nv_bfloat16 g_chi[MTOT*DD];   // ctx hi [MTOT][DD]
__device__ __align__(16) __nv_bfloat16 g_clo[MTOT*DD];

// ---------------------------------------------------------------------------
// smem tiles: 128 rows x 32 cols bf16, row stride 40 bf16 (80B), conflict-free
// ldmatrix. One buffer = 4 tiles = 40960 B. Double-buffered kernels use 81920.
// ---------------------------------------------------------------------------
#define TSTRIDE 40
#define TBYTES  (128 * TSTRIDE * 2)   // 10240
#define O_AHI 0
#define O_ALO TBYTES
#define O_BHI (2*TBYTES)
#define O_BLO (3*TBYTES)
#define BUFBYTES (4*TBYTES)           // 40960
#define DBUF_BYTES (2*BUFBYTES)       // 81920

__device__ __forceinline__ uint32_t smem_u32(const void* p) {
    uint32_t a;
    asm("{ .reg .u64 t; cvta.to.shared.u64 t, %1; cvt.u32.u64 %0, t; }" : "=r"(a) : "l"(p));
    return a;
}

__device__ __forceinline__ void ldm_x4(uint32_t* r, uint32_t addr) {
    asm volatile("ldmatrix.sync.aligned.m8n8.x4.shared.b16 {%0,%1,%2,%3}, [%4];"
                 : "=r"(r[0]), "=r"(r[1]), "=r"(r[2]), "=r"(r[3]) : "r"(addr));
}

__device__ __forceinline__ void mma16816(float* c, const uint32_t* a, const uint32_t* b) {
    asm volatile("mma.sync.aligned.m16n8k16.row.col.f32.bf16.bf16.f32 "
                 "{%0,%1,%2,%3}, {%4,%5,%6,%7}, {%8,%9}, {%0,%1,%2,%3};"
                 : "+f"(c[0]), "+f"(c[1]), "+f"(c[2]), "+f"(c[3])
                 : "r"(a[0]), "r"(a[1]), "r"(a[2]), "r"(a[3]), "r"(b[0]), "r"(b[1]));
}

__device__ __forceinline__ void cpa16(uint32_t dst, const void* src) {
    asm volatile("cp.async.ca.shared.global [%0], [%1], 16;" :: "r"(dst), "l"(src));
}
__device__ __forceinline__ void cpa_commit() {
    asm volatile("cp.async.commit_group;" ::: "memory");
}
__device__ __forceinline__ void cpa_wait0() {
    asm volatile("cp.async.wait_group 0;" ::: "memory");
}
__device__ __forceinline__ void cpa_wait1() {
    asm volatile("cp.async.wait_group 1;" ::: "memory");
}

__device__ __forceinline__ void split2(float x, uint16_t& h, uint16_t& l) {
    __nv_bfloat16 hb = __float2bfloat16(x);
    __nv_bfloat16 lb = __float2bfloat16(x - __bfloat162float(hb));
    h = *(uint16_t*)&hb;
    l = *(uint16_t*)&lb;
}
__device__ __forceinline__ uint32_t pk(uint16_t a, uint16_t b) {
    return (uint32_t)a | ((uint32_t)b << 16);
}

// ---------------------------------------------------------------------------
// Staging (256 threads)
// ---------------------------------------------------------------------------
// async copy of a 128x32 bf16 slice into stride-40 tile: 512 x 16B
__device__ __forceinline__ void stage_async(const __nv_bfloat16* src, size_t ld_e,
                                            uint32_t dst, int tid)
{
    #pragma unroll
    for (int i = 0; i < 2; i++) {
        int u = tid + i * 256;            // 0..511
        int row = u >> 2, c8 = (u & 3) * 8;
        cpa16(dst + (uint32_t)(row * TSTRIDE + c8) * 2, src + (size_t)row * ld_e + c8);
    }
}
// synchronous copy (used by proj_o)
__device__ __forceinline__ void stage_bf16_40(const __nv_bfloat16* src, size_t ld_e,
                                              uint16_t* dst, int tid)
{
    #pragma unroll
    for (int i = 0; i < 4; i++) {
        int u = tid + i * 256;
        int row = u >> 3, c4 = (u & 7) * 4;
        uint2 v = *(const uint2*)(src + (size_t)row * ld_e + c4);
        *(uint2*)(dst + row * TSTRIDE + c4) = v;
    }
}
// convert f32 128x32 slice -> hi/lo
__device__ __forceinline__ void stage_cvtA_40(const float* src, size_t ld,
                                              uint16_t* dhi, uint16_t* dlo, int tid)
{
    #pragma unroll
    for (int i = 0; i < 4; i++) {
        int u = tid + i * 256;
        int row = u >> 3, c4 = (u & 7) * 4;
        float4 v = *(const float4*)(src + (size_t)row * ld + c4);
        uint16_t hx, lx, hy, ly, hz, lz, hw, lw;
        split2(v.x, hx, lx); split2(v.y, hy, ly);
        split2(v.z, hz, lz); split2(v.w, hw, lw);
        *(uint2*)(dhi + row * TSTRIDE + c4) = make_uint2(pk(hx, hy), pk(hz, hw));
        *(uint2*)(dlo + row * TSTRIDE + c4) = make_uint2(pk(lx, ly), pk(lz, lw));
    }
}
// convert + transpose W block [32 k][128 n] f32 -> [n][k] hi/lo
__device__ __forceinline__ void stage_cvtW_40(const float* W, size_t ldw,
                                              uint16_t* dhi, uint16_t* dlo, int tid)
{
    #pragma unroll
    for (int i = 0; i < 4; i++) {
        int u = tid + i * 256;
        int kr = u >> 5, n4 = (u & 31) * 4;
        float4 v = *(const float4*)(W + (size_t)kr * ldw + n4);
        float a[4] = {v.x, v.y, v.z, v.w};
        #pragma unroll
        for (int j = 0; j < 4; j++) {
            uint16_t h, l; split2(a[j], h, l);
            dhi[(n4 + j) * TSTRIDE + kr] = h;
            dlo[(n4 + j) * TSTRIDE + kr] = l;
        }
    }
}

// ---------------------------------------------------------------------------
// Warp mainloop over one staged BK=32 chunk (buffer base = sb).
// Warp tile 64(m) x 32(n). acc[mi][ni][4].
// ---------------------------------------------------------------------------
__device__ __forceinline__ void warp_mma_chunk(float acc[4][4][4],
                                               uint32_t sb, int wm, int wn, int lane)
{
    #pragma unroll
    for (int kk = 0; kk < 32; kk += 16) {
        uint32_t Ah[4][4], Al[4][4];
        const int mrow = wm + (lane & 15);
        const int kA = kk + ((lane >> 4) << 3);
        #pragma unroll
        for (int mi = 0; mi < 4; mi++) {
            uint32_t off = (uint32_t)((mrow + mi * 16) * TSTRIDE + kA) * 2;
            ldm_x4(Ah[mi], sb + O_AHI + off);
            ldm_x4(Al[mi], sb + O_ALO + off);
        }
        const int nrow0 = wn + (lane & 7) + ((lane >> 4) << 3);
        const int kB = kk + (((lane >> 3) & 1) << 3);
        #pragma unroll
        for (int np = 0; np < 2; np++) {
            uint32_t Bh[4], Bl[4];
            uint32_t off = (uint32_t)((nrow0 + np * 16) * TSTRIDE + kB) * 2;
            ldm_x4(Bh, sb + O_BHI + off);
            ldm_x4(Bl, sb + O_BLO + off);
            #pragma unroll
            for (int mi = 0; mi < 4; mi++)
                #pragma unroll
                for (int nj = 0; nj < 2; nj++) {
                    float* c = acc[mi][np * 2 + nj];
                    mma16816(c, Ah[mi], Bh + nj * 2);
                    mma16816(c, Ah[mi], Bl + nj * 2);
                    mma16816(c, Al[mi], Bh + nj * 2);
                }
        }
    }
}

// ---------------------------------------------------------------------------
// Q/K projection: out hi/lo [MTOT][DD]  (single-buffer; convert staging)
// ---------------------------------------------------------------------------
__global__ __launch_bounds__(256) void proj_qk_mma(const float* __restrict__ A,
                                                   const float* __restrict__ W,
                                                   const float* __restrict__ bias,
                                                   __nv_bfloat16* __restrict__ dhi,
                                                   __nv_bfloat16* __restrict__ dlo)
{
    __shared__ __align__(16) uint8_t smem[BUFBYTES];
    const int tid = threadIdx.x, lane = tid & 31, wid = tid >> 5;
    const int wm = (wid & 1) * 64, wn = (wid >> 1) * 32;
    const int row0 = blockIdx.y * 128, col0 = blockIdx.x * 128;
    uint32_t sb = smem_u32(smem);
    uint16_t* sm = (uint16_t*)smem;

    float acc[4][4][4] = {};
    for (int k0 = 0; k0 < 256; k0 += 32) {
        stage_cvtA_40(A + (size_t)row0 * DD + k0, DD, sm + O_AHI/2, sm + O_ALO/2, tid);
        stage_cvtW_40(W + (size_t)k0 * DD + col0, DD, sm + O_BHI/2, sm + O_BLO/2, tid);
        __syncthreads();
        warp_mma_chunk(acc, sb, wm, wn, lane);
        __syncthreads();
    }

    const int r = lane >> 2, cq = (lane & 3) * 2;
    #pragma unroll
    for (int mi = 0; mi < 4; mi++)
        #pragma unroll
        for (int ni = 0; ni < 4; ni++) {
            int gc = col0 + wn + ni * 8 + cq;
            float b0 = bias[gc], b1 = bias[gc + 1];
            #pragma unroll
            for (int h = 0; h < 2; h++) {
                int gr = row0 + wm + mi * 16 + r + h * 8;
                float x0 = acc[mi][ni][h * 2] + b0, x1 = acc[mi][ni][h * 2 + 1] + b1;
                uint16_t h0, l0, h1, l1;
                split2(x0, h0, l0); split2(x1, h1, l1);
                *(uint32_t*)(dhi + (size_t)gr * DD + gc) = pk(h0, h1);
                *(uint32_t*)(dlo + (size_t)gr * DD + gc) = pk(l0, l1);
            }
        }
}

// ---------------------------------------------------------------------------
// V projection: out hi/lo transposed [b][d][s]
// ---------------------------------------------------------------------------
__global__ __launch_bounds__(256) void proj_v_mma(const float* __restrict__ A,
                                                  const float* __restrict__ W,
                                                  const float* __restrict__ bias,
                                                  __nv_bfloat16* __restrict__ vhi,
                                                  __nv_bfloat16* __restrict__ vlo)
{
    __shared__ __align__(16) uint8_t smem[BUFBYTES];
    const int tid = threadIdx.x, lane = tid & 31, wid = tid >> 5;
    const int wm = (wid & 1) * 64, wn = (wid >> 1) * 32;
    const int row0 = blockIdx.y * 128, col0 = blockIdx.x * 128;
    uint32_t sb = smem_u32(smem);
    uint16_t* sm = (uint16_t*)smem;

    float acc[4][4][4] = {};
    for (int k0 = 0; k0 < 256; k0 += 32) {
        stage_cvtA_40(A + (size_t)row0 * DD + k0, DD, sm + O_AHI/2, sm + O_ALO/2, tid);
        stage_cvtW_40(W + (size_t)k0 * DD + col0, DD, sm + O_BHI/2, sm + O_BLO/2, tid);
        __syncthreads();
        warp_mma_chunk(acc, sb, wm, wn, lane);
        __syncthreads();
    }

    const int r = lane >> 2, cq = (lane & 3) * 2;
    const int b = row0 >> 12, tok0 = row0 & (SS - 1);
    #pragma unroll
    for (int plane = 0; plane < 2; plane++) {
        uint16_t* tb = (uint16_t*)smem;   // [128 d][128 tok]
        #pragma unroll
        for (int mi = 0; mi < 4; mi++)
            #pragma unroll
            for (int ni = 0; ni < 4; ni++) {
                int d0 = wn + ni * 8 + cq;
                float b0 = bias[col0 + d0], b1 = bias[col0 + d0 + 1];
                #pragma unroll
                for (int h = 0; h < 2; h++) {
                    int m = wm + mi * 16 + r + h * 8;
                    float x0 = acc[mi][ni][h * 2] + b0, x1 = acc[mi][ni][h * 2 + 1] + b1;
                    uint16_t h0, l0, h1, l1;
                    split2(x0, h0, l0); split2(x1, h1, l1);
                    tb[d0 * 128 + m] = plane ? l0 : h0;
                    tb[(d0 + 1) * 128 + m] = plane ? l1 : h1;
                }
            }
        __syncthreads();
        for (int d = wid; d < 128; d += 8) {
            uint2 v = *(const uint2*)(tb + d * 128 + lane * 4);
            __nv_bfloat16* dst = (plane ? vlo : vhi) + ((size_t)b * DD + col0 + d) * SS + tok0;
            *(uint2*)((uint16_t*)dst + lane * 4) = v;
        }
        __syncthreads();
    }
}

// ---------------------------------------------------------------------------
// O projection: A = ctx hi/lo bf16, out z fp32 (+bias)
// ---------------------------------------------------------------------------
__global__ __launch_bounds__(256) void proj_o_mma(const __nv_bfloat16* __restrict__ chi,
                                                  const __nv_bfloat16* __restrict__ clo,
                                                  const float* __restrict__ W,
                                                  const float* __restrict__ bias,
                                                  float* __restrict__ z)
{
    __shared__ __align__(16) uint8_t smem[BUFBYTES];
    const int tid = threadIdx.x, lane = tid & 31, wid = tid >> 5;
    const int wm = (wid & 1) * 64, wn = (wid >> 1) * 32;
    const int row0 = blockIdx.y * 128, col0 = blockIdx.x * 128;
    uint32_t sb = smem_u32(smem);
    uint16_t* sm = (uint16_t*)smem;

    float acc[4][4][4] = {};
    for (int k0 = 0; k0 < 256; k0 += 32) {
        stage_bf16_40(chi + (size_t)row0 * DD + k0, DD, sm + O_AHI/2, tid);
        stage_bf16_40(clo + (size_t)row0 * DD + k0, DD, sm + O_ALO/2, tid);
        stage_cvtW_40(W + (size_t)k0 * DD + col0, DD, sm + O_BHI/2, sm + O_BLO/2, tid);
        __syncthreads();
        warp_mma_chunk(acc, sb, wm, wn, lane);
        __syncthreads();
    }

    const int r = lane >> 2, cq = (lane & 3) * 2;
    #pragma unroll
    for (int mi = 0; mi < 4; mi++)
        #pragma unroll
        for (int ni = 0; ni < 4; ni++) {
            int gc = col0 + wn + ni * 8 + cq;
            float b0 = bias[gc], b1 = bias[gc + 1];
            #pragma unroll
            for (int h = 0; h < 2; h++) {
                int gr = row0 + wm + mi * 16 + r + h * 8;
                float2 o = make_float2(acc[mi][ni][h * 2] + b0, acc[mi][ni][h * 2 + 1] + b1);
                *(float2*)(z + (size_t)gr * DD + gc) = o;
            }
        }
}

// ---------------------------------------------------------------------------
// Scores: logits = Q@K^T * scale (causal tiles), cp.async double-buffered
// ---------------------------------------------------------------------------
__global__ __launch_bounds__(256) void scores_mma(const __nv_bfloat16* __restrict__ qhi,
                                                  const __nv_bfloat16* __restrict__ qlo,
                                                  const __nv_bfloat16* __restrict__ khi,
                                                  const __nv_bfloat16* __restrict__ klo,
                                                  float* __restrict__ attn)
{
    const int kt = blockIdx.x, qt = blockIdx.y, b = blockIdx.z;
    if (kt > qt) return;
    extern __shared__ __align__(16) uint8_t smem[];
    const int tid = threadIdx.x, lane = tid & 31, wid = tid >> 5;
    const int wm = (wid & 1) * 64, wn = (wid >> 1) * 32;
    uint32_t sb = smem_u32(smem);

    const size_t abase = ((size_t)b * SS + qt * 128) * DD;
    const size_t bbase = ((size_t)b * SS + kt * 128) * DD;

    auto issue = [&](int c, int buf) {
        int d0 = c * 32;
        uint32_t base = sb + buf * BUFBYTES;
        stage_async(qhi + abase + d0, DD, base + O_AHI, tid);
        stage_async(qlo + abase + d0, DD, base + O_ALO, tid);
        stage_async(khi + bbase + d0, DD, base + O_BHI, tid);
        stage_async(klo + bbase + d0, DD, base + O_BLO, tid);
        cpa_commit();
    };

    float acc[4][4][4] = {};
    issue(0, 0);
    #pragma unroll 1
    for (int c = 0; c < 8; c++) {
        if (c + 1 < 8) { issue(c + 1, (c + 1) & 1); cpa_wait1(); }
        else cpa_wait0();
        __syncthreads();
        warp_mma_chunk(acc, sb + (c & 1) * BUFBYTES, wm, wn, lane);
        __syncthreads();
    }

    const int r = lane >> 2, cq = (lane & 3) * 2;
    const float scale = 0.0625f;
    #pragma unroll
    for (int mi = 0; mi < 4; mi++)
        #pragma unroll
        for (int ni = 0; ni < 4; ni++) {
            int gc = kt * 128 + wn + ni * 8 + cq;
            #pragma unroll
            for (int h = 0; h < 2; h++) {
                int gr = qt * 128 + wm + mi * 16 + r + h * 8;
                float2 o = make_float2(acc[mi][ni][h * 2] * scale,
                                       acc[mi][ni][h * 2 + 1] * scale);
                *(float2*)(attn + ((size_t)b * SS + gr) * SS + gc) = o;
            }
        }
}

// ---------------------------------------------------------------------------
// Row softmax (causal prefix); emits fp32 attn + bf16 hi/lo operand copies
// ---------------------------------------------------------------------------
__global__ __launch_bounds__(256) void softmax_kernel(float* __restrict__ attn,
                                                      __nv_bfloat16* __restrict__ ahi,
                                                      __nv_bfloat16* __restrict__ alo)
{
    __shared__ float rowbuf[SS];
    __shared__ float red[256];

    const int row = blockIdx.x;
    const int b = row >> 12;
    const int i = row & (SS - 1);
    const size_t rbase = ((size_t)b * SS + i) * SS;
    float* p = attn + rbase;
    const int n = i + 1;
    const int tid = threadIdx.x;

    float m = -3.0e38f;
    for (int j = tid; j < n; j += 256) {
        float x = p[j];
        rowbuf[j] = x;
        m = fmaxf(m, x);
    }
    red[tid] = m; __syncthreads();
    #pragma unroll
    for (int s = 128; s > 0; s >>= 1) {
        if (tid < s) red[tid] = fmaxf(red[tid], red[tid + s]);
        __syncthreads();
    }
    m = red[0];
    __syncthreads();

    float sum = 0.f;
    for (int j = tid; j < n; j += 256) {
        float e = __expf(rowbuf[j] - m);
        rowbuf[j] = e;
        sum += e;
    }
    red[tid] = sum; __syncthreads();
    #pragma unroll
    for (int s = 128; s > 0; s >>= 1) {
        if (tid < s) red[tid] += red[tid + s];
        __syncthreads();
    }
    const float inv = 1.0f / red[0];

    for (int j = tid; j < n; j += 256) {
        float a = rowbuf[j] * inv;
        p[j] = a;
        uint16_t h, l; split2(a, h, l);
        ((uint16_t*)ahi)[rbase + j] = h;
        ((uint16_t*)alo)[rbase + j] = l;
    }
    const int kend = (i & ~127) + 128;
    for (int j = n + tid; j < kend; j += 256) {
        ((uint16_t*)ahi)[rbase + j] = 0;
        ((uint16_t*)alo)[rbase + j] = 0;
    }
    for (int j = n + tid; j < SS; j += 256) p[j] = 0.0f;
}

// ---------------------------------------------------------------------------
// PV: ctx = attn @ V (causal-truncated), cp.async double-buffered
// ---------------------------------------------------------------------------
__global__ __launch_bounds__(256) void pv_mma(const __nv_bfloat16* __restrict__ ahi,
                                              const __nv_bfloat16* __restrict__ alo,
                                              const __nv_bfloat16* __restrict__ vhi,
                                              const __nv_bfloat16* __restrict__ vlo,
                                              __nv_bfloat16* __restrict__ chi,
                                              __nv_bfloat16* __restrict__ clo)
{
    const int nt = blockIdx.x, qt = blockIdx.y, b = blockIdx.z;
    extern __shared__ __align__(16) uint8_t smem[];
    const int tid = threadIdx.x, lane = tid & 31, wid = tid >> 5;
    const int wm = (wid & 1) * 64, wn = (wid >> 1) * 32;
    uint32_t sb = smem_u32(smem);

    const int NC = (qt + 1) * 4;   // BK=32 chunks up to causal boundary
    const size_t abase = ((size_t)b * SS + qt * 128) * SS;
    const size_t vbase = ((size_t)b * DD + nt * 128) * SS;

    auto issue = [&](int c, int buf) {
        int k0 = c * 32;
        uint32_t base = sb + buf * BUFBYTES;
        stage_async(ahi + abase + k0, SS, base + O_AHI, tid);
        stage_async(alo + abase + k0, SS, base + O_ALO, tid);
        stage_async(vhi + vbase + k0, SS, base + O_BHI, tid);
        stage_async(vlo + vbase + k0, SS, base + O_BLO, tid);
        cpa_commit();
    };

    float acc[4][4][4] = {};
    issue(0, 0);
    #pragma unroll 1
    for (int c = 0; c < NC; c++) {
        if (c + 1 < NC) { issue(c + 1, (c + 1) & 1); cpa_wait1(); }
        else cpa_wait0();
        __syncthreads();
        warp_mma_chunk(acc, sb + (c & 1) * BUFBYTES, wm, wn, lane);
        __syncthreads();
    }

    const int r = lane >> 2, cq = (lane & 3) * 2;
    #pragma unroll
    for (int mi = 0; mi < 4; mi++)
        #pragma unroll
        for (int ni = 0; ni < 4; ni++) {
            int gc = nt * 128 + wn + ni * 8 + cq;
            #pragma unroll
            for (int h = 0; h < 2; h++) {
                size_t gr = (size_t)b * SS + qt * 128 + wm + mi * 16 + r + h * 8;
                uint16_t h0, l0, h1, l1;
                split2(acc[mi][ni][h * 2], h0, l0);
                split2(acc[mi][ni][h * 2 + 1], h1, l1);
                *(uint32_t*)(chi + gr * DD + gc) = pk(h0, h1);
                *(uint32_t*)(clo + gr * DD + gc) = pk(l0, l1);
            }
        }
}

// ---------------------------------------------------------------------------
// Launch
// ---------------------------------------------------------------------------
extern "C" void kernel_launch(void* const* d_in, const int* in_sizes, int n_in,
                              void* d_out, int out_size)
{
    const float* q  = (const float*)d_in[0];
    const float* k  = (const float*)d_in[1];
    const float* v  = (const float*)d_in[2];
    const float* Wq = (const float*)d_in[4];
    const float* bq = (const float*)d_in[5];
    const float* Wk = (const float*)d_in[6];
    const float* bk = (const float*)d_in[7];
    const float* Wv = (const float*)d_in[8];
    const float* bv = (const float*)d_in[9];
    const float* Wo = (const float*)d_in[10];
    const float* bo = (const float*)d_in[11];

    float* z    = (float*)d_out;
    float* attn = z + (size_t)MTOT * DD;

    __nv_bfloat16 *qhi, *qlo, *khi, *klo, *vhi, *vlo, *ahi, *alo, *chi, *clo;
    cudaGetSymbolAddress((void**)&qhi, g_qhi);
    cudaGetSymbolAddress((void**)&qlo, g_qlo);
    cudaGetSymbolAddress((void**)&khi, g_khi);
    cudaGetSymbolAddress((void**)&klo, g_klo);
    cudaGetSymbolAddress((void**)&vhi, g_vhi);
    cudaGetSymbolAddress((void**)&vlo, g_vlo);
    cudaGetSymbolAddress((void**)&ahi, g_ahi);
    cudaGetSymbolAddress((void**)&alo, g_alo);
    cudaGetSymbolAddress((void**)&chi, g_chi);
    cudaGetSymbolAddress((void**)&clo, g_clo);

    cudaFuncSetAttribute(scores_mma, cudaFuncAttributeMaxDynamicSharedMemorySize, DBUF_BYTES);
    cudaFuncSetAttribute(pv_mma,     cudaFuncAttributeMaxDynamicSharedMemorySize, DBUF_BYTES);

    dim3 gproj(2, 128);
    proj_qk_mma<<<gproj, 256>>>(q, Wq, bq, qhi, qlo);
    proj_qk_mma<<<gproj, 256>>>(k, Wk, bk, khi, klo);
    proj_v_mma <<<gproj, 256>>>(v, Wv, bv, vhi, vlo);

    dim3 gsc(32, 32, 4);
    scores_mma<<<gsc, 256, DBUF_BYTES>>>(qhi, qlo, khi, klo, attn);

    softmax_kernel<<<MTOT, 256>>>(attn, ahi, alo);

    dim3 gpv(2, 32, 4);
    pv_mma<<<gpv, 256, DBUF_BYTES>>>(ahi, alo, vhi, vlo, chi, clo);

    proj_o_mma<<<gproj, 256>>>(chi, clo, Wo, bo, z);
}